// round 12
// baseline (speedup 1.0000x reference)
#include <cuda_runtime.h>
#include <cuda_fp16.h>
#include <cstdint>

#define NN 8192
#define FIN 512
#define FF 64
#define SPLIT 4
#define BM 64
#define BJ 32
#define NCH (NN / BJ)        // 256 chunks total
#define CPC (NCH / SPLIT)    // 64 chunks per CTA
#define ASTR 40              // A_s row stride in fp16 units (ldmatrix-perfect)

typedef unsigned long long ull;

// -------------------- device scratch --------------------
__device__ float g_e1[NN];
__device__ float g_e2[NN];
__device__ unsigned g_ABh[NN];                    // half2 (A', B')
__device__ __align__(16) unsigned short g_Eh[NN]; // E' fp16
__device__ __align__(16) unsigned short g_Fh[NN]; // F' fp16
__device__ float g_blockmax[128];
__device__ unsigned g_Bf[NN * 32];                // frag-major fp16 of Wh^T (1MB)
__device__ float g_num[SPLIT][NN * FF];
__device__ float g_den[SPLIT][NN];

// -------------------- helpers --------------------
__device__ __forceinline__ void cp16(void* sdst, const void* gsrc) {
    unsigned s = (unsigned)__cvta_generic_to_shared(sdst);
    asm volatile("cp.async.cg.shared.global [%0], [%1], 16;\n" :: "r"(s), "l"(gsrc));
}
#define CP_COMMIT() asm volatile("cp.async.commit_group;\n" ::: "memory")
#define CP_WAIT1()  asm volatile("cp.async.wait_group 1;\n" ::: "memory")

__device__ __forceinline__ void mma_f16(float* d, unsigned a0, unsigned a1,
                                        unsigned a2, unsigned a3,
                                        unsigned b0, unsigned b1) {
    asm("mma.sync.aligned.m16n8k16.row.col.f32.f16.f16.f32 "
        "{%0,%1,%2,%3}, {%4,%5,%6,%7}, {%8,%9}, {%0,%1,%2,%3};"
        : "+f"(d[0]), "+f"(d[1]), "+f"(d[2]), "+f"(d[3])
        : "r"(a0), "r"(a1), "r"(a2), "r"(a3), "r"(b0), "r"(b1));
}

// -------------------- K1: Wh = h @ W, fused e1/e2/blockmax/fp16-frag --------------------
__global__ __launch_bounds__(256) void k1_gemm(const float* __restrict__ h,
                                               const float* __restrict__ W,
                                               const float* __restrict__ a) {
    __shared__ __align__(16) float smemU[64 * 68];
    __shared__ float red[64];
    float* As = smemU;
    float* Bs = smemU + 2112;
    int t = threadIdx.x;
    int r0 = blockIdx.x * 64;
    int tx = t & 15;
    int ty = t >> 4;
    float acc[4][4];
#pragma unroll
    for (int i = 0; i < 4; i++)
#pragma unroll
        for (int j = 0; j < 4; j++) acc[i][j] = 0.f;

    for (int k0 = 0; k0 < FIN; k0 += 32) {
        __syncthreads();
#pragma unroll
        for (int q = 0; q < 8; q++) {
            int idx = t + 256 * q;
            int kk = idx & 31, i = idx >> 5;
            As[kk * 66 + i] = h[(r0 + i) * FIN + k0 + kk];
        }
#pragma unroll
        for (int q = 0; q < 8; q++) {
            int idx = t + 256 * q;
            int c = idx & 63, kk = idx >> 6;
            Bs[kk * 64 + c] = W[(k0 + kk) * FF + c];
        }
        __syncthreads();
#pragma unroll
        for (int kk = 0; kk < 32; kk++) {
            float2 a01 = *(const float2*)&As[kk * 66 + 4 * ty];
            float2 a23 = *(const float2*)&As[kk * 66 + 4 * ty + 2];
            float4 b = *(const float4*)&Bs[kk * 64 + 4 * tx];
            float av[4] = {a01.x, a01.y, a23.x, a23.y};
            float bv[4] = {b.x, b.y, b.z, b.w};
#pragma unroll
            for (int i = 0; i < 4; i++)
#pragma unroll
                for (int j = 0; j < 4; j++) acc[i][j] = fmaf(av[i], bv[j], acc[i][j]);
        }
    }
    __syncthreads();
    float* WhS = smemU;
#pragma unroll
    for (int i = 0; i < 4; i++) {
        float4 v = make_float4(acc[i][0], acc[i][1], acc[i][2], acc[i][3]);
        *(float4*)&WhS[(4 * ty + i) * 68 + 4 * tx] = v;
    }
    __syncthreads();
    if (t < 64) {
        const float4* wr = (const float4*)&WhS[t * 68];
        float e1 = 0.f, e2 = 0.f;
#pragma unroll
        for (int q = 0; q < 16; q++) {
            float4 v = wr[q];
            float4 a1 = *(const float4*)&a[q * 4];
            float4 a2 = *(const float4*)&a[FF + q * 4];
            e1 += v.x * a1.x + v.y * a1.y + v.z * a1.z + v.w * a1.w;
            e2 += v.x * a2.x + v.y * a2.y + v.z * a2.z + v.w * a2.w;
        }
        g_e1[r0 + t] = e1;
        g_e2[r0 + t] = e2;
        red[t] = e2;
    }
    __syncthreads();
    if (t < 32) {
        float m = fmaxf(red[t], red[t + 32]);
#pragma unroll
        for (int o = 16; o > 0; o >>= 1)
            m = fmaxf(m, __shfl_xor_sync(0xffffffffu, m, o));
        if (t == 0) g_blockmax[blockIdx.x] = m;
    }
    // fp16 frag-major conversion of this block's 64 Wh rows (j side)
    {
        int il = t >> 2, fq = t & 3;
        int j = r0 + il;
        int cch = j >> 5, kk = j & 31;
        int kt2 = kk >> 4, k2v = kk & 15;
        int rg = k2v >> 3, hf = k2v & 1, lq = (k2v & 7) >> 1;
        unsigned base = (unsigned)cch * 1024u;
        unsigned short* bp = (unsigned short*)g_Bf;
#pragma unroll
        for (int u = 0; u < 16; u++) {
            int f = fq * 16 + u;
            int ft = f >> 3, n = f & 7;
            unsigned idx32 = base + (unsigned)(((kt2 * 8 + ft) * 32 + n * 4 + lq) * 2 + rg);
            __half hv = __float2half_rn(WhS[il * 68 + f]);
            bp[idx32 * 2 + hf] = *(unsigned short*)&hv;
        }
    }
}

// -------------------- K3: global max, A'B' half2, E'/F' half arrays --------------------
__global__ __launch_bounds__(256) void k3_ef() {
    __shared__ float mred[128];
    int t = threadIdx.x;
    int i = blockIdx.x * 256 + t;
    if (t < 128) mred[t] = g_blockmax[t];
    __syncthreads();
    float m = -1e30f;
#pragma unroll
    for (int b = 0; b < 128; b++) m = fmaxf(m, mred[b]);
    float e1 = g_e1[i], e2 = g_e2[i];
    float x = e1 + m;
    float C = (x > 0.f) ? x : 0.2f * x;          // lrelu(e1 + M)
    float Ap = expf(x - C);
    float Bp = expf(0.2f * x - C);
    float Ep = expf(e2 - m);
    float Fp = expf(0.2f * (e2 - m));
    __half2 ab = __floats2half2_rn(Ap, Bp);
    g_ABh[i] = *(unsigned*)&ab;
    __half eh = __float2half_rn(Ep), fh = __float2half_rn(Fp);
    g_Eh[i] = *(unsigned short*)&eh;
    g_Fh[i] = *(unsigned short*)&fh;
}

// -------------------- K4: deep-pipelined fused adj + fp16 mma GEMM --------------------
// grid = 128 rowblocks * SPLIT(4) = 512 CTAs, 128 threads, 4 CTAs/SM, one wave.
// adj staged via cp.async ring (depth 2 chunks, thread-private consumption).
// Single CTA barrier per chunk (R10 structure).
__global__ __launch_bounds__(128, 4) void k4_main(const int* __restrict__ adj) {
    __shared__ unsigned short Ah_s[2][BM * ASTR];     // 2 x 5120 B
    __shared__ __align__(16) unsigned Bf_s[3][1024];  // 12 KB ring
    __shared__ __align__(16) int adj_s[3][BM * BJ];   // 24 KB ring

    int t = threadIdx.x;
    int lane = t & 31;
    int wid = t >> 5;                 // 0..3
    int bi = blockIdx.x & 127;
    int bs = blockIdx.x >> 7;         // 0..3
    int r0 = bi * BM;
    int cstart = bs * CPC;

    int mw = wid & 1;                 // mma rows mw*32..+31
    int nw = wid >> 1;                // mma cols nw*32..+31

    // gen mapping: thread -> (row, j-half)
    int row = t >> 1;
    int jh = t & 1;

    // row-constant scalars
    unsigned abu = g_ABh[r0 + row];
    __half2 abh = *(__half2*)&abu;
    __half2 aa = __half2half2(__low2half(abh));
    __half2 bb = __half2half2(__high2half(abh));

    const int* adjrow = adj + (size_t)(r0 + row) * NN + 16 * jh;
    const uint4* epE = (const uint4*)g_Eh;
    const uint4* epF = (const uint4*)g_Fh;

    // ldmatrix per-lane base offset (bytes) in buffer 0
    unsigned a_smem = (unsigned)__cvta_generic_to_shared(&Ah_s[0][0]);
    unsigned a_lane = a_smem +
        (unsigned)((((lane & 7) + ((lane >> 3) & 1) * 8) * ASTR + (lane >> 4) * 8) * 2);

    // prologue: stage chunks cstart, cstart+1 (adj + B), one commit group each
#pragma unroll
    for (int g = 0; g < 2; g++) {
        int c = cstart + g;
#pragma unroll
        for (int q = 0; q < 4; q++)
            cp16(&adj_s[g][t * 16 + q * 4], adjrow + (size_t)c * BJ + q * 4);
        cp16(&Bf_s[g][t * 8], &g_Bf[c * 1024 + t * 8]);
        cp16(&Bf_s[g][t * 8 + 4], &g_Bf[c * 1024 + t * 8 + 4]);
        CP_COMMIT();
    }

    // E/F register prefetch for first chunk
    uint4 ev[2], fv[2];
#pragma unroll
    for (int r = 0; r < 2; r++) {
        ev[r] = epE[cstart * 4 + 2 * jh + r];
        fv[r] = epF[cstart * 4 + 2 * jh + r];
    }

    float acc[2][4][4];
#pragma unroll
    for (int mt = 0; mt < 2; mt++)
#pragma unroll
        for (int ft = 0; ft < 4; ft++)
#pragma unroll
            for (int u = 0; u < 4; u++) acc[mt][ft][u] = 0.f;
    float dnf = 0.f;

    for (int cc = 0; cc < CPC; cc++) {
        int c = cstart + cc;
        int cur = cc & 1;
        int rb = cc % 3;

        CP_WAIT1();   // group cc done: own adj_s[rb] slice + staged B visible to self

        // gen: 16 w values for (row, 16*jh..+15) from smem adj
        const uint4* avp = (const uint4*)&adj_s[rb][t * 16];
        unsigned wv[8];
        __half2 dn2 = __float2half2_rn(0.f);
#pragma unroll
        for (int p = 0; p < 8; p++) {
            uint4 a4 = avp[p >> 1];
            unsigned a0 = (p & 1) ? a4.z : a4.x;
            unsigned a1 = (p & 1) ? a4.w : a4.y;
            unsigned eu = ((const unsigned*)ev)[p];
            unsigned fu = ((const unsigned*)fv)[p];
            __half2 w2 = __hmul2(aa, *(__half2*)&eu);
            __half2 v2 = __hmul2(bb, *(__half2*)&fu);
            w2 = __hmax2(w2, v2);
            unsigned msk = a0 * 0x3C00u + a1 * 0x3C000000u;
            w2 = __hmul2(w2, *(__half2*)&msk);
            dn2 = __hadd2(dn2, w2);
            wv[p] = *(unsigned*)&w2;
        }
        *(uint4*)&Ah_s[cur][row * ASTR + 16 * jh] =
            make_uint4(wv[0], wv[1], wv[2], wv[3]);
        *(uint4*)&Ah_s[cur][row * ASTR + 16 * jh + 8] =
            make_uint4(wv[4], wv[5], wv[6], wv[7]);
        float2 df = __half22float2(dn2);
        dnf += df.x + df.y;

        // E/F prefetch for chunk c+1
        if (cc + 1 < CPC) {
#pragma unroll
            for (int r = 0; r < 2; r++) {
                ev[r] = epE[(c + 1) * 4 + 2 * jh + r];
                fv[r] = epF[(c + 1) * 4 + 2 * jh + r];
            }
        }

        __syncthreads();   // A[cur] + B[rb] visible CTA-wide; all mma(cc-1) done

        // stage chunk cc+2 (post-barrier: ring WAR safe), always commit a group
        if (cc + 2 < CPC) {
            int cn = c + 2;
            int wb = (cc + 2) % 3;
#pragma unroll
            for (int q = 0; q < 4; q++)
                cp16(&adj_s[wb][t * 16 + q * 4], adjrow + (size_t)cn * BJ + q * 4);
            cp16(&Bf_s[wb][t * 8], &g_Bf[cn * 1024 + t * 8]);
            cp16(&Bf_s[wb][t * 8 + 4], &g_Bf[cn * 1024 + t * 8 + 4]);
        }
        CP_COMMIT();

        // mma: warp computes 32x32 slice
#pragma unroll
        for (int kt = 0; kt < 2; kt++) {
            uint2 bfr[4];
#pragma unroll
            for (int ft = 0; ft < 4; ft++) {
                int ftg = nw * 4 + ft;
                bfr[ft] = *(const uint2*)&Bf_s[rb][((kt * 8 + ftg) * 32 + lane) * 2];
            }
#pragma unroll
            for (int mt = 0; mt < 2; mt++) {
                unsigned addr = a_lane + (unsigned)(cur * (BM * ASTR * 2)) +
                    (unsigned)(((mw * 32 + mt * 16) * ASTR + kt * 16) * 2);
                unsigned a0, a1, a2, a3;
                asm("ldmatrix.sync.aligned.m8n8.x4.shared.b16 {%0,%1,%2,%3}, [%4];"
                    : "=r"(a0), "=r"(a1), "=r"(a2), "=r"(a3) : "r"(addr));
#pragma unroll
                for (int ft = 0; ft < 4; ft++)
                    mma_f16(acc[mt][ft], a0, a1, a2, a3, bfr[ft].x, bfr[ft].y);
            }
        }
    }

    // write numerator partials
#pragma unroll
    for (int mt = 0; mt < 2; mt++) {
        int r1 = r0 + mw * 32 + mt * 16 + (lane >> 2);
#pragma unroll
        for (int ft = 0; ft < 4; ft++) {
            int col = nw * 32 + ft * 8 + (lane & 3) * 2;
            *(float2*)&g_num[bs][r1 * FF + col] = make_float2(acc[mt][ft][0], acc[mt][ft][1]);
            *(float2*)&g_num[bs][(r1 + 8) * FF + col] = make_float2(acc[mt][ft][2], acc[mt][ft][3]);
        }
    }
    // denominator: combine the two j-halves of each row
    float dn = dnf + __shfl_xor_sync(0xffffffffu, dnf, 1);
    if (jh == 0) g_den[bs][r0 + row] = dn;
}

// -------------------- K5: reduce splits, normalize, ELU --------------------
__global__ __launch_bounds__(256) void k5_out(float* __restrict__ out) {
    int idx4 = blockIdx.x * 256 + threadIdx.x;
    int idx = idx4 * 4;
    int i = idx >> 6;
    float4 num = make_float4(0.f, 0.f, 0.f, 0.f);
    float den = 0.f;
#pragma unroll
    for (int s = 0; s < SPLIT; s++) {
        float4 v = *(const float4*)&g_num[s][idx];
        num.x += v.x; num.y += v.y; num.z += v.z; num.w += v.w;
        den += g_den[s][i];
    }
    den = fmaxf(den, 1e-30f);
    float r = 1.f / den;
    float4 o;
    o.x = num.x * r; o.y = num.y * r; o.z = num.z * r; o.w = num.w * r;
    o.x = (o.x > 0.f) ? o.x : expm1f(o.x);
    o.y = (o.y > 0.f) ? o.y : expm1f(o.y);
    o.z = (o.z > 0.f) ? o.z : expm1f(o.z);
    o.w = (o.w > 0.f) ? o.w : expm1f(o.w);
    *(float4*)&out[idx] = o;
}

// -------------------- launch --------------------
extern "C" void kernel_launch(void* const* d_in, const int* in_sizes, int n_in,
                              void* d_out, int out_size) {
    const float* h = (const float*)d_in[0];
    const int* adj = (const int*)d_in[1];
    const float* W = (const float*)d_in[2];
    const float* a = (const float*)d_in[3];
    float* out = (float*)d_out;

    k1_gemm<<<NN / 64, 256>>>(h, W, a);
    k3_ef<<<NN / 256, 256>>>();
    k4_main<<<128 * SPLIT, 128>>>(adj);
    k5_out<<<(NN * FF) / 1024, 256>>>(out);
}

// round 13
// speedup vs baseline: 1.3859x; 1.3859x over previous
#include <cuda_runtime.h>
#include <cuda_fp16.h>
#include <cstdint>

#define NN 8192
#define FIN 512
#define FF 64
#define SPLIT 5
#define BM 64
#define BJ 32
#define NCH (NN / BJ)        // 256 chunks total
#define ASTR 40              // A_s row stride in fp16 units (ldmatrix-perfect)

typedef unsigned long long ull;

// -------------------- device scratch --------------------
__device__ float g_e1[NN];
__device__ float g_e2[NN];
__device__ unsigned g_ABh[NN];                    // half2 (A', B')
__device__ __align__(16) unsigned short g_Eh[NN]; // E' fp16
__device__ __align__(16) unsigned short g_Fh[NN]; // F' fp16
__device__ float g_blockmax[128];
__device__ unsigned g_Bf[NN * 32];                // frag-major fp16 of Wh^T (1MB)
__device__ float g_num[SPLIT][NN * FF];
__device__ float g_den[SPLIT][NN];

// -------------------- helpers --------------------
__device__ __forceinline__ void cp16(void* sdst, const void* gsrc) {
    unsigned s = (unsigned)__cvta_generic_to_shared(sdst);
    asm volatile("cp.async.cg.shared.global [%0], [%1], 16;\n" :: "r"(s), "l"(gsrc));
}
#define CP_COMMIT() asm volatile("cp.async.commit_group;\n" ::: "memory")
#define CP_WAIT0()  asm volatile("cp.async.wait_group 0;\n" ::: "memory")

__device__ __forceinline__ void mma_f16(float* d, unsigned a0, unsigned a1,
                                        unsigned a2, unsigned a3,
                                        unsigned b0, unsigned b1) {
    asm("mma.sync.aligned.m16n8k16.row.col.f32.f16.f16.f32 "
        "{%0,%1,%2,%3}, {%4,%5,%6,%7}, {%8,%9}, {%0,%1,%2,%3};"
        : "+f"(d[0]), "+f"(d[1]), "+f"(d[2]), "+f"(d[3])
        : "r"(a0), "r"(a1), "r"(a2), "r"(a3), "r"(b0), "r"(b1));
}

// -------------------- K1: Wh = h @ W, fused e1/e2/blockmax/fp16-frag --------------------
__global__ __launch_bounds__(256) void k1_gemm(const float* __restrict__ h,
                                               const float* __restrict__ W,
                                               const float* __restrict__ a) {
    __shared__ __align__(16) float smemU[64 * 68];
    __shared__ float red[64];
    float* As = smemU;
    float* Bs = smemU + 2112;
    int t = threadIdx.x;
    int r0 = blockIdx.x * 64;
    int tx = t & 15;
    int ty = t >> 4;
    float acc[4][4];
#pragma unroll
    for (int i = 0; i < 4; i++)
#pragma unroll
        for (int j = 0; j < 4; j++) acc[i][j] = 0.f;

    for (int k0 = 0; k0 < FIN; k0 += 32) {
        __syncthreads();
#pragma unroll
        for (int q = 0; q < 8; q++) {
            int idx = t + 256 * q;
            int kk = idx & 31, i = idx >> 5;
            As[kk * 66 + i] = h[(r0 + i) * FIN + k0 + kk];
        }
#pragma unroll
        for (int q = 0; q < 8; q++) {
            int idx = t + 256 * q;
            int c = idx & 63, kk = idx >> 6;
            Bs[kk * 64 + c] = W[(k0 + kk) * FF + c];
        }
        __syncthreads();
#pragma unroll
        for (int kk = 0; kk < 32; kk++) {
            float2 a01 = *(const float2*)&As[kk * 66 + 4 * ty];
            float2 a23 = *(const float2*)&As[kk * 66 + 4 * ty + 2];
            float4 b = *(const float4*)&Bs[kk * 64 + 4 * tx];
            float av[4] = {a01.x, a01.y, a23.x, a23.y};
            float bv[4] = {b.x, b.y, b.z, b.w};
#pragma unroll
            for (int i = 0; i < 4; i++)
#pragma unroll
                for (int j = 0; j < 4; j++) acc[i][j] = fmaf(av[i], bv[j], acc[i][j]);
        }
    }
    __syncthreads();
    float* WhS = smemU;
#pragma unroll
    for (int i = 0; i < 4; i++) {
        float4 v = make_float4(acc[i][0], acc[i][1], acc[i][2], acc[i][3]);
        *(float4*)&WhS[(4 * ty + i) * 68 + 4 * tx] = v;
    }
    __syncthreads();
    if (t < 64) {
        const float4* wr = (const float4*)&WhS[t * 68];
        float e1 = 0.f, e2 = 0.f;
#pragma unroll
        for (int q = 0; q < 16; q++) {
            float4 v = wr[q];
            float4 a1 = *(const float4*)&a[q * 4];
            float4 a2 = *(const float4*)&a[FF + q * 4];
            e1 += v.x * a1.x + v.y * a1.y + v.z * a1.z + v.w * a1.w;
            e2 += v.x * a2.x + v.y * a2.y + v.z * a2.z + v.w * a2.w;
        }
        g_e1[r0 + t] = e1;
        g_e2[r0 + t] = e2;
        red[t] = e2;
    }
    __syncthreads();
    if (t < 32) {
        float m = fmaxf(red[t], red[t + 32]);
#pragma unroll
        for (int o = 16; o > 0; o >>= 1)
            m = fmaxf(m, __shfl_xor_sync(0xffffffffu, m, o));
        if (t == 0) g_blockmax[blockIdx.x] = m;
    }
    // fp16 frag-major conversion of this block's 64 Wh rows (j side)
    {
        int il = t >> 2, fq = t & 3;
        int j = r0 + il;
        int cch = j >> 5, kk = j & 31;
        int kt2 = kk >> 4, k2v = kk & 15;
        int rg = k2v >> 3, hf = k2v & 1, lq = (k2v & 7) >> 1;
        unsigned base = (unsigned)cch * 1024u;
        unsigned short* bp = (unsigned short*)g_Bf;
#pragma unroll
        for (int u = 0; u < 16; u++) {
            int f = fq * 16 + u;
            int ft = f >> 3, n = f & 7;
            unsigned idx32 = base + (unsigned)(((kt2 * 8 + ft) * 32 + n * 4 + lq) * 2 + rg);
            __half hv = __float2half_rn(WhS[il * 68 + f]);
            bp[idx32 * 2 + hf] = *(unsigned short*)&hv;
        }
    }
}

// -------------------- K3: global max, A'B' half2, E'/F' half arrays --------------------
__global__ __launch_bounds__(256) void k3_ef() {
    __shared__ float mred[128];
    int t = threadIdx.x;
    int i = blockIdx.x * 256 + t;
    if (t < 128) mred[t] = g_blockmax[t];
    __syncthreads();
    float m = -1e30f;
#pragma unroll
    for (int b = 0; b < 128; b++) m = fmaxf(m, mred[b]);
    float e1 = g_e1[i], e2 = g_e2[i];
    float x = e1 + m;
    float C = (x > 0.f) ? x : 0.2f * x;          // lrelu(e1 + M)
    float Ap = expf(x - C);
    float Bp = expf(0.2f * x - C);
    float Ep = expf(e2 - m);
    float Fp = expf(0.2f * (e2 - m));
    __half2 ab = __floats2half2_rn(Ap, Bp);
    g_ABh[i] = *(unsigned*)&ab;
    __half eh = __float2half_rn(Ep), fh = __float2half_rn(Fp);
    g_Eh[i] = *(unsigned short*)&eh;
    g_Fh[i] = *(unsigned short*)&fh;
}

// -------------------- K4: fused adj + fp16 mma attention GEMM --------------------
// grid = 128 rowblocks * SPLIT(5) = 640 CTAs, 128 threads, 5 CTAs/SM.
// Gen lane remap: (rql = lane>>3, jb = lane&7) -> 8 lanes read one row's full
// 128B adj line per LDG.128 (4 fully-used lines per load, was 16 partial).
__global__ __launch_bounds__(128, 5) void k4_main(const int* __restrict__ adj) {
    __shared__ unsigned short Ah_s[2][BM * ASTR];     // 2 x 5120 B
    __shared__ __align__(16) unsigned Bf_s[2][1024];  // 8192 B

    int t = threadIdx.x;
    int lane = t & 31;
    int wid = t >> 5;                 // 0..3
    int bi = blockIdx.x & 127;
    int bs = blockIdx.x >> 7;         // 0..4
    int r0 = bi * BM;
    int cstart = bs * 51 + (bs > 0 ? 1 : 0);
    int cend = cstart + 51 + (bs == 0 ? 1 : 0);

    int mw = wid & 1;                 // mma rows mw*32..+31
    int nw = wid >> 1;                // mma cols nw*32..+31

    // gen mapping: lane -> (row sub, j block of 4)
    int rql = lane >> 3;              // 0..3
    int jb = lane & 7;                // j = 4*jb .. 4*jb+3

    // row-constant scalars for this thread's 4 rows (local rows wid*16+4q+rql)
    __half2 aa[4], bb[4];
    const uint4* adjp[4];
#pragma unroll
    for (int q = 0; q < 4; q++) {
        int rl = wid * 16 + 4 * q + rql;
        unsigned abu = g_ABh[r0 + rl];
        __half2 abh = *(__half2*)&abu;
        aa[q] = __half2half2(__low2half(abh));
        bb[q] = __half2half2(__high2half(abh));
        adjp[q] = (const uint4*)(adj + (size_t)(r0 + rl) * NN + 4 * jb);
    }
    const uint2* epE = (const uint2*)g_Eh;
    const uint2* epF = (const uint2*)g_Fh;

    // ldmatrix per-lane base offset (bytes) in buffer 0
    unsigned a_smem = (unsigned)__cvta_generic_to_shared(&Ah_s[0][0]);
    unsigned a_lane = a_smem +
        (unsigned)((((lane & 7) + ((lane >> 3) & 1) * 8) * ASTR + (lane >> 4) * 8) * 2);

    // prologue: B stage + adj/E/F regs for first chunk
    cp16(&Bf_s[cstart & 1][t * 8], &g_Bf[cstart * 1024 + t * 8]);
    cp16(&Bf_s[cstart & 1][t * 8 + 4], &g_Bf[cstart * 1024 + t * 8 + 4]);
    CP_COMMIT();

    uint4 av[4];
    uint2 eu, fu;
#pragma unroll
    for (int q = 0; q < 4; q++) av[q] = adjp[q][(size_t)cstart * 8];
    eu = epE[cstart * 8 + jb];
    fu = epF[cstart * 8 + jb];

    float acc[2][4][4];
#pragma unroll
    for (int mt = 0; mt < 2; mt++)
#pragma unroll
        for (int ft = 0; ft < 4; ft++)
#pragma unroll
            for (int u = 0; u < 4; u++) acc[mt][ft][u] = 0.f;
    float dnf[4] = {0.f, 0.f, 0.f, 0.f};

    for (int c = cstart; c < cend; c++) {
        int cur = c & 1;

        // gen: 4 rows x 4 j values each
        __half2 e01 = *(__half2*)&eu.x;
        __half2 e23 = *(__half2*)&eu.y;
        __half2 f01 = *(__half2*)&fu.x;
        __half2 f23 = *(__half2*)&fu.y;
#pragma unroll
        for (int q = 0; q < 4; q++) {
            uint4 a4 = av[q];
            __half2 w0 = __hmax2(__hmul2(aa[q], e01), __hmul2(bb[q], f01));
            unsigned m0 = a4.x * 0x3C00u + a4.y * 0x3C000000u;
            w0 = __hmul2(w0, *(__half2*)&m0);
            __half2 w1 = __hmax2(__hmul2(aa[q], e23), __hmul2(bb[q], f23));
            unsigned m1 = a4.z * 0x3C00u + a4.w * 0x3C000000u;
            w1 = __hmul2(w1, *(__half2*)&m1);
            __half2 dn2 = __hadd2(w0, w1);
            float2 df = __half22float2(dn2);
            dnf[q] += df.x + df.y;
            int rl = wid * 16 + 4 * q + rql;
            *(uint2*)&Ah_s[cur][rl * ASTR + 4 * jb] =
                make_uint2(*(unsigned*)&w0, *(unsigned*)&w1);
        }

        // prefetch next chunk's adj/E/F
        if (c + 1 < cend) {
#pragma unroll
            for (int q = 0; q < 4; q++) av[q] = adjp[q][(size_t)(c + 1) * 8];
            eu = epE[(c + 1) * 8 + jb];
            fu = epF[(c + 1) * 8 + jb];
        }

        CP_WAIT0();        // B[cur] landed
        __syncthreads();   // A[cur] + B[cur] visible; all mma(c-1) done

        // issue next B prefetch (race-free: everyone past mma(c-1))
        if (c + 1 < cend) {
            cp16(&Bf_s[cur ^ 1][t * 8], &g_Bf[(c + 1) * 1024 + t * 8]);
            cp16(&Bf_s[cur ^ 1][t * 8 + 4], &g_Bf[(c + 1) * 1024 + t * 8 + 4]);
            CP_COMMIT();
        }

        // mma: warp computes 32x32 slice
#pragma unroll
        for (int kt = 0; kt < 2; kt++) {
            uint2 bfr[4];
#pragma unroll
            for (int ft = 0; ft < 4; ft++) {
                int ftg = nw * 4 + ft;
                bfr[ft] = *(const uint2*)&Bf_s[cur][((kt * 8 + ftg) * 32 + lane) * 2];
            }
#pragma unroll
            for (int mt = 0; mt < 2; mt++) {
                unsigned addr = a_lane + (unsigned)(cur * (BM * ASTR * 2)) +
                    (unsigned)(((mw * 32 + mt * 16) * ASTR + kt * 16) * 2);
                unsigned a0, a1, a2, a3;
                asm("ldmatrix.sync.aligned.m8n8.x4.shared.b16 {%0,%1,%2,%3}, [%4];"
                    : "=r"(a0), "=r"(a1), "=r"(a2), "=r"(a3) : "r"(addr));
#pragma unroll
                for (int ft = 0; ft < 4; ft++)
                    mma_f16(acc[mt][ft], a0, a1, a2, a3, bfr[ft].x, bfr[ft].y);
            }
        }
    }

    // write numerator partials
#pragma unroll
    for (int mt = 0; mt < 2; mt++) {
        int r1 = r0 + mw * 32 + mt * 16 + (lane >> 2);
#pragma unroll
        for (int ft = 0; ft < 4; ft++) {
            int col = nw * 32 + ft * 8 + (lane & 3) * 2;
            *(float2*)&g_num[bs][r1 * FF + col] = make_float2(acc[mt][ft][0], acc[mt][ft][1]);
            *(float2*)&g_num[bs][(r1 + 8) * FF + col] = make_float2(acc[mt][ft][2], acc[mt][ft][3]);
        }
    }
    // denominator: reduce each row's partial over the 8 jb lanes
#pragma unroll
    for (int q = 0; q < 4; q++) {
        float v = dnf[q];
        v += __shfl_xor_sync(0xffffffffu, v, 1);
        v += __shfl_xor_sync(0xffffffffu, v, 2);
        v += __shfl_xor_sync(0xffffffffu, v, 4);
        if (jb == 0) g_den[bs][r0 + wid * 16 + 4 * q + rql] = v;
    }
}

// -------------------- K5: reduce splits, normalize, ELU --------------------
__global__ __launch_bounds__(256) void k5_out(float* __restrict__ out) {
    int idx4 = blockIdx.x * 256 + threadIdx.x;
    int idx = idx4 * 4;
    int i = idx >> 6;
    float4 num = make_float4(0.f, 0.f, 0.f, 0.f);
    float den = 0.f;
#pragma unroll
    for (int s = 0; s < SPLIT; s++) {
        float4 v = *(const float4*)&g_num[s][idx];
        num.x += v.x; num.y += v.y; num.z += v.z; num.w += v.w;
        den += g_den[s][i];
    }
    den = fmaxf(den, 1e-30f);
    float r = 1.f / den;
    float4 o;
    o.x = num.x * r; o.y = num.y * r; o.z = num.z * r; o.w = num.w * r;
    o.x = (o.x > 0.f) ? o.x : expm1f(o.x);
    o.y = (o.y > 0.f) ? o.y : expm1f(o.y);
    o.z = (o.z > 0.f) ? o.z : expm1f(o.z);
    o.w = (o.w > 0.f) ? o.w : expm1f(o.w);
    *(float4*)&out[idx] = o;
}

// -------------------- launch --------------------
extern "C" void kernel_launch(void* const* d_in, const int* in_sizes, int n_in,
                              void* d_out, int out_size) {
    const float* h = (const float*)d_in[0];
    const int* adj = (const int*)d_in[1];
    const float* W = (const float*)d_in[2];
    const float* a = (const float*)d_in[3];
    float* out = (float*)d_out;

    k1_gemm<<<NN / 64, 256>>>(h, W, a);
    k3_ef<<<NN / 256, 256>>>();
    k4_main<<<128 * SPLIT, 128>>>(adj);
    k5_out<<<(NN * FF) / 1024, 256>>>(out);
}